// round 10
// baseline (speedup 1.0000x reference)
#include <cuda_runtime.h>

// ButterflyLinear: 12 butterfly stages on N=4096, TOKENS=8192.
// Stage 0 pairs (j, j^1); stages 1..11 all pair (j, j^2) => transform is
// block-diagonal in 4-element groups: out = blockdiag(A_g) * x + bias.
//
// SINGLE kernel, deadlock-free soft grid barrier, with the R9 lesson fixed:
// every block issues its first 4 stream loads BEFORE the fold/spin, so the
// barrier latency is hidden under the first DRAM round-trip instead of
// serializing in front of it.
//  - first 16 ticket-holding blocks (running by construction) fold the 4096
//    (group,column) tasks into g_C exactly once;
//  - all blocks spin on a completion flag (volatile loads), then run the
//    proven R7 streaming body (37.6us standalone, ~70% DRAM ceiling);
//  - last finishing block resets flags -> deterministic per replay.

#define TOKENS 8192
#define NCOLS  4096
#define DEPTH  12
#define GROUPS (NCOLS / 4)   // 1024
#define PAIRS  (NCOLS / 2)   // 2048 factor pairs per stage
#define T_PER  8             // tokens per thread -> 4096 blocks
#define FOLD_BLOCKS 16       // 16 blocks x 256 threads = 4096 fold tasks

// g_C[g*4+e] = column e of A_g = (A[0][e], A[1][e], A[2][e], A[3][e]); 64KB.
__device__ float4   g_C[GROUPS * 4];
__device__ unsigned g_ticket   = 0;
__device__ unsigned g_folddone = 0;
__device__ unsigned g_finished = 0;

// ---------------------------------------------------------------------------
// Fold one (group, column) task. Column-separable recurrence; loads batched
// 4 stages at a time. factors: F[stage][pair] as float4
// (f.x=f[0][0], f.y=f[0][1], f.z=f[1][0], f.w=f[1][1]);
// stage semantics y[d] = sum_c in[c]*f[c][d].
// ---------------------------------------------------------------------------
__device__ __forceinline__ void fold_task(int idx, const float4* __restrict__ F4) {
    int g = idx >> 2;
    int e = idx & 3;
    int j0 = 4 * g;

    float A0, A1, A2, A3;
    {
        float4 f0 = F4[2 * g];
        float4 f1 = F4[2 * g + 1];
        bool lo = (e < 2);
        float4 f = lo ? f0 : f1;
        float u = (e & 1) ? f.z : f.x;
        float v = (e & 1) ? f.w : f.y;
        A0 = lo ? u : 0.f;
        A1 = lo ? v : 0.f;
        A2 = lo ? 0.f : u;
        A3 = lo ? 0.f : v;
    }

    #pragma unroll
    for (int c0 = 1; c0 < DEPTH; c0 += 4) {
        float4 fa[4], fb[4];
        #pragma unroll
        for (int k = 0; k < 4; k++) {
            int s = c0 + k;
            if (s < DEPTH) {
                int block = 1 << (s + 1);
                int pA = ((j0 >> (s + 1)) << s) | ((j0 & (block - 1)) >> 2);
                int pB = pA + (1 << (s - 1));
                fa[k] = F4[s * PAIRS + pA];
                fb[k] = F4[s * PAIRS + pB];
            }
        }
        #pragma unroll
        for (int k = 0; k < 4; k++) {
            int s = c0 + k;
            if (s < DEPTH) {
                float r0 = A0, r1 = A1, r2 = A2, r3 = A3;
                A0 = fa[k].x * r0 + fa[k].z * r2;
                A2 = fa[k].y * r0 + fa[k].w * r2;
                A1 = fb[k].x * r1 + fb[k].z * r3;
                A3 = fb[k].y * r1 + fb[k].w * r3;
            }
        }
    }

    g_C[idx] = make_float4(A0, A1, A2, A3);
}

// ---------------------------------------------------------------------------
__global__ void __launch_bounds__(256, 5)
butterfly_one(const float4* __restrict__ F4,
              const float4* __restrict__ x,
              const float4* __restrict__ bias4,
              float4* __restrict__ out) {
    int g  = blockIdx.x * blockDim.x + threadIdx.x;  // 0..GROUPS-1
    int t0 = blockIdx.y * T_PER;

    const float4* xp = x   + (size_t)t0 * GROUPS + g;
    float4*       op = out + (size_t)t0 * GROUPS + g;

    // ---- prefetch first 4 stream tokens BEFORE the barrier (independent
    //      of g_C; scoreboard keeps them in flight across the spin) ----
    float4 v0 = __ldcs(xp + 0 * GROUPS);
    float4 v1 = __ldcs(xp + 1 * GROUPS);
    float4 v2 = __ldcs(xp + 2 * GROUPS);
    float4 v3 = __ldcs(xp + 3 * GROUPS);

    // ---- ticket: first FOLD_BLOCKS blocks (running by construction) fold ----
    __shared__ unsigned s_tk;
    if (threadIdx.x == 0) s_tk = atomicAdd(&g_ticket, 1u);
    __syncthreads();
    unsigned tk = s_tk;

    if (tk < FOLD_BLOCKS) {
        fold_task((int)(tk * 256 + threadIdx.x), F4);
        __threadfence();
        __syncthreads();                 // all 256 fold writes fenced
        if (threadIdx.x == 0) atomicAdd(&g_folddone, 1u);
    }

    // ---- wait for the fold (overlapped with the prefetches above) ----
    if (threadIdx.x == 0) {
        while (*(volatile unsigned*)&g_folddone < FOLD_BLOCKS) __nanosleep(128);
    }
    __syncthreads();
    __threadfence();

    // ---- streaming phase: exact R7 body ----
    float4 c0 = g_C[g * 4 + 0];
    float4 c1 = g_C[g * 4 + 1];
    float4 c2 = g_C[g * 4 + 2];
    float4 c3 = g_C[g * 4 + 3];
    float4 b  = bias4[g];

    #pragma unroll
    for (int ii = 0; ii < T_PER; ii += 4) {
        if (ii > 0) {
            v0 = __ldcs(xp + (size_t)(ii + 0) * GROUPS);
            v1 = __ldcs(xp + (size_t)(ii + 1) * GROUPS);
            v2 = __ldcs(xp + (size_t)(ii + 2) * GROUPS);
            v3 = __ldcs(xp + (size_t)(ii + 3) * GROUPS);
        }

        float4 r0, r1, r2, r3;
        r0.x = b.x + v0.x*c0.x + v0.y*c1.x + v0.z*c2.x + v0.w*c3.x;
        r0.y = b.y + v0.x*c0.y + v0.y*c1.y + v0.z*c2.y + v0.w*c3.y;
        r0.z = b.z + v0.x*c0.z + v0.y*c1.z + v0.z*c2.z + v0.w*c3.z;
        r0.w = b.w + v0.x*c0.w + v0.y*c1.w + v0.z*c2.w + v0.w*c3.w;

        r1.x = b.x + v1.x*c0.x + v1.y*c1.x + v1.z*c2.x + v1.w*c3.x;
        r1.y = b.y + v1.x*c0.y + v1.y*c1.y + v1.z*c2.y + v1.w*c3.y;
        r1.z = b.z + v1.x*c0.z + v1.y*c1.z + v1.z*c2.z + v1.w*c3.z;
        r1.w = b.w + v1.x*c0.w + v1.y*c1.w + v1.z*c2.w + v1.w*c3.w;

        r2.x = b.x + v2.x*c0.x + v2.y*c1.x + v2.z*c2.x + v2.w*c3.x;
        r2.y = b.y + v2.x*c0.y + v2.y*c1.y + v2.z*c2.y + v2.w*c3.y;
        r2.z = b.z + v2.x*c0.z + v2.y*c1.z + v2.z*c2.z + v2.w*c3.z;
        r2.w = b.w + v2.x*c0.w + v2.y*c1.w + v2.z*c2.w + v2.w*c3.w;

        r3.x = b.x + v3.x*c0.x + v3.y*c1.x + v3.z*c2.x + v3.w*c3.x;
        r3.y = b.y + v3.x*c0.y + v3.y*c1.y + v3.z*c2.y + v3.w*c3.y;
        r3.z = b.z + v3.x*c0.z + v3.y*c1.z + v3.z*c2.z + v3.w*c3.z;
        r3.w = b.w + v3.x*c0.w + v3.y*c1.w + v3.z*c2.w + v3.w*c3.w;

        __stcs(op + (size_t)(ii + 0) * GROUPS, r0);
        __stcs(op + (size_t)(ii + 1) * GROUPS, r1);
        __stcs(op + (size_t)(ii + 2) * GROUPS, r2);
        __stcs(op + (size_t)(ii + 3) * GROUPS, r3);
    }

    // ---- last block resets flags so every replay starts from zero ----
    if (threadIdx.x == 0) {
        __threadfence();
        unsigned nb = gridDim.x * gridDim.y;
        unsigned f = atomicAdd(&g_finished, 1u);
        if (f == nb - 1u) {
            g_ticket   = 0;
            g_folddone = 0;
            g_finished = 0;
            __threadfence();
        }
    }
}

// ---------------------------------------------------------------------------
extern "C" void kernel_launch(void* const* d_in, const int* in_sizes, int n_in,
                              void* d_out, int out_size) {
    const float* x = nullptr;
    const float* factors = nullptr;
    const float* bias = nullptr;
    for (int i = 0; i < n_in; i++) {
        if (in_sizes[i] == TOKENS * NCOLS)            x = (const float*)d_in[i];
        else if (in_sizes[i] == DEPTH * PAIRS * 4)    factors = (const float*)d_in[i];
        else if (in_sizes[i] == NCOLS)                bias = (const float*)d_in[i];
    }

    dim3 grid(GROUPS / 256, TOKENS / T_PER);   // (4, 1024) = 4096 blocks
    butterfly_one<<<grid, 256>>>((const float4*)factors,
                                 (const float4*)x,
                                 (const float4*)bias,
                                 (float4*)d_out);
}

// round 11
// speedup vs baseline: 1.0887x; 1.0887x over previous
#include <cuda_runtime.h>

// ButterflyLinear: 12 butterfly stages on N=4096, TOKENS=8192.
// Stage 0 pairs (j, j^1); stages 1..11 all pair (j, j^2) => transform is
// block-diagonal in 4-element groups. Kernel 1 folds per-group 4x4s
// (column-parallel, 4096 threads). Kernel 2 streams out = blockdiag(A)*x + b.
// R11 change: apply front-batches ALL 8 token loads (MLP_p1 = 8, double the
// per-warp outstanding-load depth) under a 64-reg cap; occupancy drops to
// ~4 CTA/SM which R5-R8 showed is still on the flat part of the BW curve.

#define TOKENS 8192
#define NCOLS  4096
#define DEPTH  12
#define GROUPS (NCOLS / 4)   // 1024
#define PAIRS  (NCOLS / 2)   // 2048 factor pairs per stage
#define T_PER  8             // tokens per thread -> 4096 blocks

// Scratch: 1024 groups x 4 columns (each column = float4) = 64 KB.
// g_C[g*4+e] = (A[0][e], A[1][e], A[2][e], A[3][e])
__device__ float4 g_C[GROUPS * 4];

// ---------------------------------------------------------------------------
// Kernel 1: one thread per (group, column); column-separable fold with
// front-batched MLP=24 loads (one DRAM round-trip).
// factors layout: F[stage][pair][c][d] as float4 per pair:
//   f.x=f[0][0], f.y=f[0][1], f.z=f[1][0], f.w=f[1][1]
// Stage semantics: y[d] = sum_c pair_in[c] * f[c][d]
// ---------------------------------------------------------------------------
__global__ void butterfly_precompute(const float4* __restrict__ F4) {
    int t = blockIdx.x * blockDim.x + threadIdx.x;   // 0..4095
    int g = t >> 2;
    int e = t & 3;
    int j0 = 4 * g;

    float4 fa[DEPTH], fb[DEPTH];
    fa[0] = F4[2 * g];
    fb[0] = F4[2 * g + 1];
    #pragma unroll
    for (int s = 1; s < DEPTH; s++) {
        int block = 1 << (s + 1);
        int pA = ((j0 >> (s + 1)) << s) | ((j0 & (block - 1)) >> 2);
        int pB = pA + (1 << (s - 1));
        fa[s] = F4[s * PAIRS + pA];
        fb[s] = F4[s * PAIRS + pB];
    }

    float A0, A1, A2, A3;
    {
        float4 f0 = fa[0], f1 = fb[0];
        bool lo = (e < 2);
        float4 f = lo ? f0 : f1;
        float u = (e & 1) ? f.z : f.x;
        float v = (e & 1) ? f.w : f.y;
        A0 = lo ? u : 0.f;
        A1 = lo ? v : 0.f;
        A2 = lo ? 0.f : u;
        A3 = lo ? 0.f : v;
    }

    #pragma unroll
    for (int s = 1; s < DEPTH; s++) {
        float a00 = fa[s].x, a01 = fa[s].y, a10 = fa[s].z, a11 = fa[s].w;
        float b00 = fb[s].x, b01 = fb[s].y, b10 = fb[s].z, b11 = fb[s].w;
        float r0 = A0, r1 = A1, r2 = A2, r3 = A3;
        A0 = a00 * r0 + a10 * r2;
        A2 = a01 * r0 + a11 * r2;
        A1 = b00 * r1 + b10 * r3;
        A3 = b01 * r1 + b11 * r3;
    }

    g_C[t] = make_float4(A0, A1, A2, A3);
}

// ---------------------------------------------------------------------------
// Kernel 2: out[t, group g] = A_g * x[t, g] + bias_g (column-major A):
//   r = b + v.x*c0 + v.y*c1 + v.z*c2 + v.w*c3
// All 8 token loads issued before any compute/store: MLP_p1 = 8.
// ---------------------------------------------------------------------------
__global__ void __launch_bounds__(256, 4)
butterfly_apply(const float4* __restrict__ x,
                const float4* __restrict__ bias4,
                float4* __restrict__ out) {
    int g  = blockIdx.x * blockDim.x + threadIdx.x;  // 0..GROUPS-1
    int t0 = blockIdx.y * T_PER;

    const float4* xp = x   + (size_t)t0 * GROUPS + g;
    float4*       op = out + (size_t)t0 * GROUPS + g;

    // ---- all 8 loads in flight before anything else ----
    float4 v0 = __ldcs(xp + 0 * GROUPS);
    float4 v1 = __ldcs(xp + 1 * GROUPS);
    float4 v2 = __ldcs(xp + 2 * GROUPS);
    float4 v3 = __ldcs(xp + 3 * GROUPS);
    float4 v4 = __ldcs(xp + 4 * GROUPS);
    float4 v5 = __ldcs(xp + 5 * GROUPS);
    float4 v6 = __ldcs(xp + 6 * GROUPS);
    float4 v7 = __ldcs(xp + 7 * GROUPS);

    float4 c0 = g_C[g * 4 + 0];
    float4 c1 = g_C[g * 4 + 1];
    float4 c2 = g_C[g * 4 + 2];
    float4 c3 = g_C[g * 4 + 3];
    float4 b  = bias4[g];

    float4 r0, r1, r2, r3;
    r0.x = b.x + v0.x*c0.x + v0.y*c1.x + v0.z*c2.x + v0.w*c3.x;
    r0.y = b.y + v0.x*c0.y + v0.y*c1.y + v0.z*c2.y + v0.w*c3.y;
    r0.z = b.z + v0.x*c0.z + v0.y*c1.z + v0.z*c2.z + v0.w*c3.z;
    r0.w = b.w + v0.x*c0.w + v0.y*c1.w + v0.z*c2.w + v0.w*c3.w;

    r1.x = b.x + v1.x*c0.x + v1.y*c1.x + v1.z*c2.x + v1.w*c3.x;
    r1.y = b.y + v1.x*c0.y + v1.y*c1.y + v1.z*c2.y + v1.w*c3.y;
    r1.z = b.z + v1.x*c0.z + v1.y*c1.z + v1.z*c2.z + v1.w*c3.z;
    r1.w = b.w + v1.x*c0.w + v1.y*c1.w + v1.z*c2.w + v1.w*c3.w;

    r2.x = b.x + v2.x*c0.x + v2.y*c1.x + v2.z*c2.x + v2.w*c3.x;
    r2.y = b.y + v2.x*c0.y + v2.y*c1.y + v2.z*c2.y + v2.w*c3.y;
    r2.z = b.z + v2.x*c0.z + v2.y*c1.z + v2.z*c2.z + v2.w*c3.z;
    r2.w = b.w + v2.x*c0.w + v2.y*c1.w + v2.z*c2.w + v2.w*c3.w;

    r3.x = b.x + v3.x*c0.x + v3.y*c1.x + v3.z*c2.x + v3.w*c3.x;
    r3.y = b.y + v3.x*c0.y + v3.y*c1.y + v3.z*c2.y + v3.w*c3.y;
    r3.z = b.z + v3.x*c0.z + v3.y*c1.z + v3.z*c2.z + v3.w*c3.z;
    r3.w = b.w + v3.x*c0.w + v3.y*c1.w + v3.z*c2.w + v3.w*c3.w;

    __stcs(op + 0 * GROUPS, r0);
    __stcs(op + 1 * GROUPS, r1);
    __stcs(op + 2 * GROUPS, r2);
    __stcs(op + 3 * GROUPS, r3);

    // v0..v3 registers are dead now; reuse the same r registers.
    r0.x = b.x + v4.x*c0.x + v4.y*c1.x + v4.z*c2.x + v4.w*c3.x;
    r0.y = b.y + v4.x*c0.y + v4.y*c1.y + v4.z*c2.y + v4.w*c3.y;
    r0.z = b.z + v4.x*c0.z + v4.y*c1.z + v4.z*c2.z + v4.w*c3.z;
    r0.w = b.w + v4.x*c0.w + v4.y*c1.w + v4.z*c2.w + v4.w*c3.w;

    r1.x = b.x + v5.x*c0.x + v5.y*c1.x + v5.z*c2.x + v5.w*c3.x;
    r1.y = b.y + v5.x*c0.y + v5.y*c1.y + v5.z*c2.y + v5.w*c3.y;
    r1.z = b.z + v5.x*c0.z + v5.y*c1.z + v5.z*c2.z + v5.w*c3.z;
    r1.w = b.w + v5.x*c0.w + v5.y*c1.w + v5.z*c2.w + v5.w*c3.w;

    r2.x = b.x + v6.x*c0.x + v6.y*c1.x + v6.z*c2.x + v6.w*c3.x;
    r2.y = b.y + v6.x*c0.y + v6.y*c1.y + v6.z*c2.y + v6.w*c3.y;
    r2.z = b.z + v6.x*c0.z + v6.y*c1.z + v6.z*c2.z + v6.w*c3.z;
    r2.w = b.w + v6.x*c0.w + v6.y*c1.w + v6.z*c2.w + v6.w*c3.w;

    r3.x = b.x + v7.x*c0.x + v7.y*c1.x + v7.z*c2.x + v7.w*c3.x;
    r3.y = b.y + v7.x*c0.y + v7.y*c1.y + v7.z*c2.y + v7.w*c3.y;
    r3.z = b.z + v7.x*c0.z + v7.y*c1.z + v7.z*c2.z + v7.w*c3.z;
    r3.w = b.w + v7.x*c0.w + v7.y*c1.w + v7.z*c2.w + v7.w*c3.w;

    __stcs(op + 4 * GROUPS, r0);
    __stcs(op + 5 * GROUPS, r1);
    __stcs(op + 6 * GROUPS, r2);
    __stcs(op + 7 * GROUPS, r3);
}

// ---------------------------------------------------------------------------
extern "C" void kernel_launch(void* const* d_in, const int* in_sizes, int n_in,
                              void* d_out, int out_size) {
    const float* x = nullptr;
    const float* factors = nullptr;
    const float* bias = nullptr;
    for (int i = 0; i < n_in; i++) {
        if (in_sizes[i] == TOKENS * NCOLS)            x = (const float*)d_in[i];
        else if (in_sizes[i] == DEPTH * PAIRS * 4)    factors = (const float*)d_in[i];
        else if (in_sizes[i] == NCOLS)                bias = (const float*)d_in[i];
    }

    // Kernel 1: 4096 threads = 1 per (group, column).
    butterfly_precompute<<<32, 128>>>((const float4*)factors);

    // Kernel 2: (4, 1024) = 4096 blocks, 8 tokens per thread.
    dim3 grid(GROUPS / 256, TOKENS / T_PER);
    butterfly_apply<<<grid, 256>>>((const float4*)x,
                                   (const float4*)bias,
                                   (float4*)d_out);
}